// round 6
// baseline (speedup 1.0000x reference)
#include <cuda_runtime.h>
#include <cstdint>

#define NS 512          // number of sites N
#define CHUNK 16        // sites per lane (32 lanes * 16 = 512)
#define WPB 3           // warps per block
#define BPW 2           // batches per warp
#define THREADS (WPB * 32)

// A coefficients for site n = l*16 + k at idx = k*32 + l, packed as
// 9 floats across two float4 planes + one float plane:
//   a4 = (c00.x, c00.y, c00.z, c01.x), b4 = (c01.y, c01.z, c11.x, c11.y), s = c11.z
// where cP = (A_xx, A_xy+A_yx, A_yy) for upper-tri element P of M.
__device__ float4 g_A4a[NS];
__device__ float4 g_A4b[NS];
__device__ float  g_A1[NS];

__global__ void prep_A_kernel(const float* __restrict__ mpo) {
    int n = blockIdx.x * blockDim.x + threadIdx.x;
    if (n >= NS) return;
    const float inv = 1.0f / (1.5707963267948966f + 1e-5f); // 1/PI_HALF
    int l = n >> 4, k = n & 15;
    int idx = k * 32 + l;
    float c[9];
    #pragma unroll
    for (int p = 0; p < 3; p++) {
        int li = (p == 2) ? 1 : 0;
        int ri = (p == 0) ? 0 : 1;
        const float* m = mpo + n * 16 + li * 8 + ri * 4; // mpo[n,li,ri,:,:]
        c[p * 3 + 0] = atanf(m[0]) * inv;
        c[p * 3 + 1] = (atanf(m[1]) + atanf(m[2])) * inv;
        c[p * 3 + 2] = atanf(m[3]) * inv;
    }
    g_A4a[idx] = make_float4(c[0], c[1], c[2], c[3]);
    g_A4b[idx] = make_float4(c[4], c[5], c[6], c[7]);
    g_A1[idx]  = c[8];
}

// ||(a,b)|| via rsqrt, safe when a*a+b*b flushes to 0.
__device__ __forceinline__ float safe_norm(float a, float b) {
    float r2 = fmaf(a, a, b * b);
    float nm = r2 * rsqrtf(r2);
    return (r2 > 0.f) ? nm : 0.f;
}

__global__ void __launch_bounds__(THREADS, 4)
tdvp_kernel(const float* __restrict__ x,
            const float* __restrict__ scale_p,
            float* __restrict__ out,
            int B)
{
    __shared__ float4 sA4a[NS];            //  8192 B
    __shared__ float4 sA4b[NS];            //  8192 B
    __shared__ float  sA1[NS];             //  2048 B
    __shared__ float2 sX[WPB][BPW][NS];    // 24576 B  (total 43008 B)

    int tid = threadIdx.x;
    for (int i = tid; i < NS; i += THREADS) {
        sA4a[i] = g_A4a[i];
        sA4b[i] = g_A4b[i];
        sA1[i]  = g_A1[i];
    }
    __syncthreads();

    const int lane = tid & 31;
    const int warp = tid >> 5;
    const int b0 = (blockIdx.x * WPB + warp) * BPW;
    if (b0 >= B) return;   // B even => b0+1 < B whenever b0 < B

    const float scale = __ldg(scale_p);

    // ---- Stage x for both batches: coalesced float4 loads -> swizzled smem.
    // Site n = l*16 + k at sX[warp][j][k*32 + (l ^ k)] as float2.
    #pragma unroll
    for (int j = 0; j < BPW; j++) {
        const float4* xg = reinterpret_cast<const float4*>(x + (size_t)(b0 + j) * (NS * 2));
        float2* sxj = sX[warp][j];
        #pragma unroll
        for (int it = 0; it < 8; it++) {
            float4 v = xg[it * 32 + lane];
            int n0 = (it * 32 + lane) * 2;
            int l0 = n0 >> 4;
            int k0 = n0 & 15;
            sxj[k0 * 32 + (l0 ^ k0)] = make_float2(v.x, v.y);
            sxj[(k0 + 1) * 32 + (l0 ^ (k0 + 1))] = make_float2(v.z, v.w);
        }
    }
    __syncwarp();

    const int nbase = lane * CHUNK;

    // ---- Pass A: one A read per site, used for BOTH batches.
    float M00[BPW][CHUNK], M01[BPW][CHUNK], M11[BPW][CHUNK];
    float ca[BPW], cb[BPW], cd[BPW];
    #pragma unroll
    for (int j = 0; j < BPW; j++) { ca[j] = 1.f; cb[j] = 0.f; cd[j] = 1.f; }

    #pragma unroll
    for (int k = 0; k < CHUNK; k++) {
        const int ai = k * 32 + lane;
        float4 a4 = sA4a[ai];
        float4 b4 = sA4b[ai];
        float  s1 = sA1[ai];
        #pragma unroll
        for (int j = 0; j < BPW; j++) {
            float2 xv = sX[warp][j][k * 32 + (lane ^ k)];
            float rnx = rsqrtf(fmaf(xv.x, xv.x, xv.y * xv.y));
            float u0 = xv.x * rnx, u1 = xv.y * rnx;
            float p = u0 * u0, q = u0 * u1, r = u1 * u1;
            float m00 = fmaf(p, a4.x, fmaf(q, a4.y, r * a4.z));
            float m01 = fmaf(p, a4.w, fmaf(q, b4.x, r * b4.y));
            float m11 = fmaf(p, b4.z, fmaf(q, b4.w, r * s1));
            M00[j][k] = m00; M01[j][k] = m01; M11[j][k] = m11;
            float na = ca[j] * m00;
            float nb = fmaf(ca[j], m01, cb[j] * m11);
            cd[j] = cd[j] * m11;
            ca[j] = na; cb[j] = nb;
        }
    }
    __syncwarp();   // sX reads done; buffers reused as scratch below

    // ---- Warp Kogge-Stone inclusive PREFIX scans (both batches interleaved).
    float pa[BPW], pb[BPW], pd[BPW];
    #pragma unroll
    for (int j = 0; j < BPW; j++) { pa[j] = ca[j]; pb[j] = cb[j]; pd[j] = cd[j]; }
    #pragma unroll
    for (int off = 1; off < 32; off <<= 1) {
        #pragma unroll
        for (int j = 0; j < BPW; j++) {
            float na = __shfl_up_sync(0xffffffffu, pa[j], off);
            float nb = __shfl_up_sync(0xffffffffu, pb[j], off);
            float nd = __shfl_up_sync(0xffffffffu, pd[j], off);
            if (lane >= off) {
                float ta = na * pa[j];
                float tb = fmaf(na, pb[j], nb * pd[j]);
                float td = nd * pd[j];
                pa[j] = ta; pb[j] = tb; pd[j] = td;
            }
        }
    }
    float T01[BPW], ea[BPW], eb[BPW];
    #pragma unroll
    for (int j = 0; j < BPW; j++) {
        T01[j] = __shfl_sync(0xffffffffu, pb[j], 31);
        ea[j] = __shfl_up_sync(0xffffffffu, pa[j], 1);
        eb[j] = __shfl_up_sync(0xffffffffu, pb[j], 1);
        if (lane == 0) { ea[j] = 1.f; eb[j] = 0.f; }
    }

    // ---- Warp inclusive SUFFIX scans; exclusive tail (col1 only).
    float sa[BPW], sb2[BPW], sd2[BPW];
    #pragma unroll
    for (int j = 0; j < BPW; j++) { sa[j] = ca[j]; sb2[j] = cb[j]; sd2[j] = cd[j]; }
    #pragma unroll
    for (int off = 1; off < 32; off <<= 1) {
        #pragma unroll
        for (int j = 0; j < BPW; j++) {
            float na = __shfl_down_sync(0xffffffffu, sa[j], off);
            float nb = __shfl_down_sync(0xffffffffu, sb2[j], off);
            float nd = __shfl_down_sync(0xffffffffu, sd2[j], off);
            if (lane + off < 32) {
                float ta = sa[j] * na;
                float tb = fmaf(sa[j], nb, sb2[j] * nd);
                float td = sd2[j] * nd;
                sa[j] = ta; sb2[j] = tb; sd2[j] = td;
            }
        }
    }
    float esb[BPW], esd[BPW];
    #pragma unroll
    for (int j = 0; j < BPW; j++) {
        esb[j] = __shfl_down_sync(0xffffffffu, sb2[j], 1);
        esd[j] = __shfl_down_sync(0xffffffffu, sd2[j], 1);
        if (lane == 31) { esb[j] = 0.f; esd[j] = 1.f; }
    }

    // ---- Backward walks (interleaved): rn = ||S[n+1] col1|| + eps
    //      (exact 1 at n=N-1), stored to swizzled per-warp/batch scratch.
    float* rnS[BPW];
    #pragma unroll
    for (int j = 0; j < BPW; j++) rnS[j] = reinterpret_cast<float*>(sX[warp][j]);
    {
        float Sb[BPW], Sd[BPW];
        #pragma unroll
        for (int j = 0; j < BPW; j++) { Sb[j] = esb[j]; Sd[j] = esd[j]; }
        #pragma unroll
        for (int k = CHUNK - 1; k >= 0; k--) {
            #pragma unroll
            for (int j = 0; j < BPW; j++) {
                float rv = (nbase + k == NS - 1) ? 1.0f : (safe_norm(Sb[j], Sd[j]) + 1e-6f);
                rnS[j][k * 32 + (lane ^ k)] = rv;
                float nSb = fmaf(M00[j][k], Sb[j], M01[j][k] * Sd[j]);
                Sd[j] = M11[j][k] * Sd[j];
                Sb[j] = nSb;
            }
        }
    }

    // ---- Forward walks (interleaved): pn = ||P[n-1] row0|| + eps (1 at n=0);
    //      w = 1/(pn*rn); store w back to scratch; accumulate sum(w).
    float ra[BPW], rb[BPW], sumw[BPW];
    #pragma unroll
    for (int j = 0; j < BPW; j++) { ra[j] = ea[j]; rb[j] = eb[j]; sumw[j] = 0.f; }
    #pragma unroll
    for (int k = 0; k < CHUNK; k++) {
        #pragma unroll
        for (int j = 0; j < BPW; j++) {
            float pn = (nbase + k == 0) ? 1.0f : (safe_norm(ra[j], rb[j]) + 1e-6f);
            float w = __fdividef(1.0f, pn * rnS[j][k * 32 + (lane ^ k)]);
            rnS[j][k * 32 + (lane ^ k)] = w;
            sumw[j] += w;
            float nra = ra[j] * M00[j][k];
            rb[j] = fmaf(ra[j], M01[j][k], rb[j] * M11[j][k]);
            ra[j] = nra;
        }
    }

    // ---- Reduce sums; fold relu + L1 normalization into one factor each.
    #pragma unroll
    for (int off = 16; off; off >>= 1) {
        #pragma unroll
        for (int j = 0; j < BPW; j++)
            sumw[j] += __shfl_xor_sync(0xffffffffu, sumw[j], off);
    }
    float f[BPW];
    #pragma unroll
    for (int j = 0; j < BPW; j++) {
        float c = scale * T01[j];
        f[j] = (c > 0.f) ? __fdividef(c, fmaf(c, sumw[j], 1e-6f)) : 0.f;
    }
    __syncwarp();   // all lanes' w in scratch before cross-lane reads

    // ---- Fully-coalesced output: lane stores float4 #(it*32+lane).
    #pragma unroll
    for (int j = 0; j < BPW; j++) {
        float* ob = out + (size_t)(b0 + j) * NS;
        const float* ws = rnS[j];
        #pragma unroll
        for (int it = 0; it < 4; it++) {
            int fi = it * 32 + lane;        // float4 index; sites 4*fi..4*fi+3
            float4 v;
            #pragma unroll
            for (int c = 0; c < 4; c++) {
                int n = fi * 4 + c;
                int kk = n & 15, ll = n >> 4;
                (&v.x)[c] = ws[kk * 32 + (ll ^ kk)] * f[j];
            }
            reinterpret_cast<float4*>(ob)[fi] = v;
        }
    }
}

extern "C" void kernel_launch(void* const* d_in, const int* in_sizes, int n_in,
                              void* d_out, int out_size) {
    const float* x     = (const float*)d_in[0]; // (B, N, 2)
    const float* mpo   = (const float*)d_in[1]; // (N, 2, 2, 2, 2)
    const float* scale = (const float*)d_in[2]; // scalar
    float* out = (float*)d_out;                 // (B, N)

    int B = in_sizes[0] / (NS * 2);

    prep_A_kernel<<<(NS + 255) / 256, 256>>>(mpo);
    int blocks = (B + WPB * BPW - 1) / (WPB * BPW);
    tdvp_kernel<<<blocks, THREADS>>>(x, scale, out, B);
}

// round 7
// speedup vs baseline: 1.0755x; 1.0755x over previous
#include <cuda_runtime.h>
#include <cstdint>

#define NS 512          // number of sites N
#define CHUNK 16        // sites per lane (32 lanes * 16 = 512)
#define HALF 8
#define WPB 4           // warps (batches) per block
#define THREADS (WPB * 32)

// A coefficients for site n = l*16 + k at idx = k*32 + l, packed as
// 9 floats across two float4 planes + one float plane:
//   a4 = (c00.x, c00.y, c00.z, c01.x), b4 = (c01.y, c01.z, c11.x, c11.y), s = c11.z
// where cP = (A_xx, A_xy+A_yx, A_yy) for upper-tri element P of M.
__device__ float4 g_A4a[NS];
__device__ float4 g_A4b[NS];
__device__ float  g_A1[NS];

__global__ void prep_A_kernel(const float* __restrict__ mpo) {
    int n = blockIdx.x * blockDim.x + threadIdx.x;
    if (n >= NS) return;
    const float inv = 1.0f / (1.5707963267948966f + 1e-5f); // 1/PI_HALF
    int l = n >> 4, k = n & 15;
    int idx = k * 32 + l;
    float c[9];
    #pragma unroll
    for (int p = 0; p < 3; p++) {
        int li = (p == 2) ? 1 : 0;
        int ri = (p == 0) ? 0 : 1;
        const float* m = mpo + n * 16 + li * 8 + ri * 4; // mpo[n,li,ri,:,:]
        c[p * 3 + 0] = atanf(m[0]) * inv;
        c[p * 3 + 1] = (atanf(m[1]) + atanf(m[2])) * inv;
        c[p * 3 + 2] = atanf(m[3]) * inv;
    }
    g_A4a[idx] = make_float4(c[0], c[1], c[2], c[3]);
    g_A4b[idx] = make_float4(c[4], c[5], c[6], c[7]);
    g_A1[idx]  = c[8];
}

// ||(a,b)|| via rsqrt, safe when a*a+b*b flushes to 0.
__device__ __forceinline__ float safe_norm(float a, float b) {
    float r2 = fmaf(a, a, b * b);
    float nm = r2 * rsqrtf(r2);
    return (r2 > 0.f) ? nm : 0.f;
}

__global__ void __launch_bounds__(THREADS, 5)
tdvp_kernel(const float* __restrict__ x,
            const float* __restrict__ scale_p,
            float* __restrict__ out,
            int B)
{
    __shared__ float4 sA4a[NS];           //  8192 B
    __shared__ float4 sA4b[NS];           //  8192 B
    __shared__ float  sA1[NS];            //  2048 B
    __shared__ float2 sX[WPB][NS];        // 16384 B  (total 34816 B)

    int tid = threadIdx.x;
    for (int i = tid; i < NS; i += THREADS) {
        sA4a[i] = g_A4a[i];
        sA4b[i] = g_A4b[i];
        sA1[i]  = g_A1[i];
    }
    __syncthreads();

    const int lane = tid & 31;
    const int warp = tid >> 5;
    const int b = blockIdx.x * WPB + warp;
    if (b >= B) return;

    const float scale = __ldg(scale_p);

    // ---- Stage x: coalesced float4 loads -> transposed swizzled smem.
    // Site n = l*16 + k at sX[warp][k*32 + (l ^ k)] as float2.
    float2* sx = sX[warp];
    {
        const float4* xg = reinterpret_cast<const float4*>(x + (size_t)b * (NS * 2));
        #pragma unroll
        for (int it = 0; it < 8; it++) {
            float4 v = xg[it * 32 + lane];
            int n0 = (it * 32 + lane) * 2;
            int l0 = n0 >> 4;
            int k0 = n0 & 15;
            sx[k0 * 32 + (l0 ^ k0)] = make_float2(v.x, v.y);
            sx[(k0 + 1) * 32 + (l0 ^ (k0 + 1))] = make_float2(v.z, v.w);
        }
        __syncwarp();
    }

    const int nbase = lane * CHUNK;

    // ---- Pass A: build M per site; accumulate TWO independent half-aggregates
    //      (lo over k=0..7, hi over k=8..15) for ILP-2 chains.
    float M00[CHUNK], M01[CHUNK], M11[CHUNK];
    float la = 1.f, lb = 0.f, ld = 1.f;
    float ha = 1.f, hb = 0.f, hd = 1.f;
    #pragma unroll
    for (int k = 0; k < HALF; k++) {
        // low-half site k
        {
            float2 xv = sx[k * 32 + (lane ^ k)];
            float rnx = rsqrtf(fmaf(xv.x, xv.x, xv.y * xv.y));
            float u0 = xv.x * rnx, u1 = xv.y * rnx;
            float p = u0 * u0, q = u0 * u1, r = u1 * u1;
            const int ai = k * 32 + lane;
            float4 a4 = sA4a[ai];
            float4 b4 = sA4b[ai];
            float  s1 = sA1[ai];
            float m00 = fmaf(p, a4.x, fmaf(q, a4.y, r * a4.z));
            float m01 = fmaf(p, a4.w, fmaf(q, b4.x, r * b4.y));
            float m11 = fmaf(p, b4.z, fmaf(q, b4.w, r * s1));
            M00[k] = m00; M01[k] = m01; M11[k] = m11;
            float na = la * m00;
            float nb = fmaf(la, m01, lb * m11);
            ld = ld * m11;
            la = na; lb = nb;
        }
        // high-half site k+8
        {
            const int kk = k + HALF;
            float2 xv = sx[kk * 32 + (lane ^ kk)];
            float rnx = rsqrtf(fmaf(xv.x, xv.x, xv.y * xv.y));
            float u0 = xv.x * rnx, u1 = xv.y * rnx;
            float p = u0 * u0, q = u0 * u1, r = u1 * u1;
            const int ai = kk * 32 + lane;
            float4 a4 = sA4a[ai];
            float4 b4 = sA4b[ai];
            float  s1 = sA1[ai];
            float m00 = fmaf(p, a4.x, fmaf(q, a4.y, r * a4.z));
            float m01 = fmaf(p, a4.w, fmaf(q, b4.x, r * b4.y));
            float m11 = fmaf(p, b4.z, fmaf(q, b4.w, r * s1));
            M00[kk] = m00; M01[kk] = m01; M11[kk] = m11;
            float na = ha * m00;
            float nb = fmaf(ha, m01, hb * m11);
            hd = hd * m11;
            ha = na; hb = nb;
        }
    }
    // Full chunk aggregate C = L ∘ H (upper-tri compose).
    float ca = la * ha;
    float cb = fmaf(la, hb, lb * hd);
    float cd = ld * hd;

    // ---- Interleaved warp Kogge-Stone scans: inclusive PREFIX and SUFFIX.
    float pa = ca, pb = cb, pd = cd;      // prefix
    float sa = ca, sb2 = cb, sd2 = cd;    // suffix
    #pragma unroll
    for (int off = 1; off < 32; off <<= 1) {
        float upa = __shfl_up_sync(0xffffffffu, pa, off);
        float upb = __shfl_up_sync(0xffffffffu, pb, off);
        float upd = __shfl_up_sync(0xffffffffu, pd, off);
        float dna = __shfl_down_sync(0xffffffffu, sa, off);
        float dnb = __shfl_down_sync(0xffffffffu, sb2, off);
        float dnd = __shfl_down_sync(0xffffffffu, sd2, off);
        if (lane >= off) {
            float ta = upa * pa;
            float tb = fmaf(upa, pb, upb * pd);
            float td = upd * pd;
            pa = ta; pb = tb; pd = td;
        }
        if (lane + off < 32) {
            float ta = sa * dna;
            float tb = fmaf(sa, dnb, sb2 * dnd);
            float td = sd2 * dnd;
            sa = ta; sb2 = tb; sd2 = td;
        }
    }
    float T01 = __shfl_sync(0xffffffffu, pb, 31);   // full-chain (0,1) entry
    float ea = __shfl_up_sync(0xffffffffu, pa, 1);
    float eb = __shfl_up_sync(0xffffffffu, pb, 1);
    if (lane == 0) { ea = 1.f; eb = 0.f; }
    float esb = __shfl_down_sync(0xffffffffu, sb2, 1);
    float esd = __shfl_down_sync(0xffffffffu, sd2, 1);
    if (lane == 31) { esb = 0.f; esd = 1.f; }

    // ---- Backward walk, both halves concurrently (ILP 2), rn in registers.
    // hi half seeds from (esb,esd); lo half from H ∘ S_tail col1.
    float rn[CHUNK];
    {
        float Sbh = esb, Sdh = esd;
        float Sbl = fmaf(ha, esb, hb * esd);
        float Sdl = hd * esd;
        #pragma unroll
        for (int s = 0; s < HALF; s++) {
            const int kh = CHUNK - 1 - s;
            rn[kh] = (nbase + kh == NS - 1) ? 1.0f : (safe_norm(Sbh, Sdh) + 1e-6f);
            float nb = fmaf(M00[kh], Sbh, M01[kh] * Sdh);
            Sdh = M11[kh] * Sdh;
            Sbh = nb;

            const int kl = HALF - 1 - s;   // never site N-1
            rn[kl] = safe_norm(Sbl, Sdl) + 1e-6f;
            float nb2 = fmaf(M00[kl], Sbl, M01[kl] * Sdl);
            Sdl = M11[kl] * Sdl;
            Sbl = nb2;
        }
    }

    // ---- Forward walk, both halves concurrently; w = 1/(pn*rn) off-path.
    float sumw = 0.f;
    {
        float ral = ea, rbl = eb;
        float rah = ea * la;
        float rbh = fmaf(ea, lb, eb * ld);
        #pragma unroll
        for (int s = 0; s < HALF; s++) {
            const int kl = s;
            float pnl = (nbase + kl == 0) ? 1.0f : (safe_norm(ral, rbl) + 1e-6f);
            float wl = __fdividef(1.0f, pnl * rn[kl]);
            rn[kl] = wl;
            sumw += wl;
            float na = ral * M00[kl];
            rbl = fmaf(ral, M01[kl], rbl * M11[kl]);
            ral = na;

            const int kh = s + HALF;       // never site 0
            float pnh = safe_norm(rah, rbh) + 1e-6f;
            float wh = __fdividef(1.0f, pnh * rn[kh]);
            rn[kh] = wh;
            sumw += wh;
            float na2 = rah * M00[kh];
            rbh = fmaf(rah, M01[kh], rbh * M11[kh]);
            rah = na2;
        }
    }

    // ---- Reduce sum(w); fold relu + L1 normalization into one factor.
    #pragma unroll
    for (int off = 16; off; off >>= 1)
        sumw += __shfl_xor_sync(0xffffffffu, sumw, off);

    float c = scale * T01;
    float f = (c > 0.f) ? __fdividef(c, fmaf(c, sumw, 1e-6f)) : 0.f;

    // ---- Direct per-lane float4 stores (sites nbase..nbase+15).
    float* ob = out + (size_t)b * NS + nbase;
    #pragma unroll
    for (int k = 0; k < CHUNK; k += 4) {
        float4 v;
        v.x = rn[k + 0] * f;
        v.y = rn[k + 1] * f;
        v.z = rn[k + 2] * f;
        v.w = rn[k + 3] * f;
        *reinterpret_cast<float4*>(ob + k) = v;
    }
}

extern "C" void kernel_launch(void* const* d_in, const int* in_sizes, int n_in,
                              void* d_out, int out_size) {
    const float* x     = (const float*)d_in[0]; // (B, N, 2)
    const float* mpo   = (const float*)d_in[1]; // (N, 2, 2, 2, 2)
    const float* scale = (const float*)d_in[2]; // scalar
    float* out = (float*)d_out;                 // (B, N)

    int B = in_sizes[0] / (NS * 2);

    prep_A_kernel<<<(NS + 255) / 256, 256>>>(mpo);
    int blocks = (B + WPB - 1) / WPB;
    tdvp_kernel<<<blocks, THREADS>>>(x, scale, out, B);
}

// round 8
// speedup vs baseline: 1.0768x; 1.0012x over previous
#include <cuda_runtime.h>
#include <cstdint>

#define NS 512          // number of sites
#define CHUNK 8         // sites per lane (2 warps x 32 lanes x 8 = 512)
#define WARPS 8         // warps per block = 4 batches
#define THREADS 256

// A coefficients for site n = h*256 + l*8 + k at idx = h*256 + k*32 + l,
// packed as two float4 planes + one float plane (9 coeffs):
//   a4 = (c00.x, c00.y, c00.z, c01.x), b4 = (c01.y, c01.z, c11.x, c11.y), s = c11.z
// where cP = (A_xx, A_xy+A_yx, A_yy) for upper-tri element P of M.
__device__ float4 g_A4a[NS];
__device__ float4 g_A4b[NS];
__device__ float  g_A1[NS];

__global__ void prep_A_kernel(const float* __restrict__ mpo) {
    int n = blockIdx.x * blockDim.x + threadIdx.x;
    if (n >= NS) return;
    const float inv = 1.0f / (1.5707963267948966f + 1e-5f); // 1/PI_HALF
    int h = n >> 8, l = (n >> 3) & 31, k = n & 7;
    int idx = h * 256 + k * 32 + l;
    float c[9];
    #pragma unroll
    for (int p = 0; p < 3; p++) {
        int li = (p == 2) ? 1 : 0;
        int ri = (p == 0) ? 0 : 1;
        const float* m = mpo + n * 16 + li * 8 + ri * 4; // mpo[n,li,ri,:,:]
        c[p * 3 + 0] = atanf(m[0]) * inv;
        c[p * 3 + 1] = (atanf(m[1]) + atanf(m[2])) * inv;
        c[p * 3 + 2] = atanf(m[3]) * inv;
    }
    g_A4a[idx] = make_float4(c[0], c[1], c[2], c[3]);
    g_A4b[idx] = make_float4(c[4], c[5], c[6], c[7]);
    g_A1[idx]  = c[8];
}

// ||(a,b)|| via rsqrt, safe when a*a+b*b flushes to 0.
__device__ __forceinline__ float safe_norm(float a, float b) {
    float r2 = fmaf(a, a, b * b);
    float nm = r2 * rsqrtf(r2);
    return (r2 > 0.f) ? nm : 0.f;
}

__global__ void __launch_bounds__(THREADS, 4)
tdvp_kernel(const float* __restrict__ x,
            const float* __restrict__ scale_p,
            float* __restrict__ out,
            int B)
{
    __shared__ float4 sA4a[NS];           //  8192 B
    __shared__ float4 sA4b[NS];           //  8192 B
    __shared__ float  sA1[NS];            //  2048 B
    __shared__ float2 sX[WARPS][256];     // 16384 B
    __shared__ float  sT[WARPS][4];       // warp-chunk totals (a,b,d)
    __shared__ float  sWp[WARPS];         // per-warp partial sums
    // total ~34.9 KB

    int tid = threadIdx.x;
    for (int i = tid; i < NS; i += THREADS) {
        sA4a[i] = g_A4a[i];
        sA4b[i] = g_A4b[i];
        sA1[i]  = g_A1[i];
    }
    __syncthreads();

    const int lane = tid & 31;
    const int warp = tid >> 5;
    const int half = warp & 1;            // which 256-site half of the batch
    const int pair = warp >> 1;
    const int b = blockIdx.x * (WARPS / 2) + pair;

    const float scale = __ldg(scale_p);

    // ---- Stage this warp's 256 sites: 4 coalesced float4 loads -> swizzled smem.
    // Site (local) nl = l*8 + k stored at sx[k*32 + (l ^ (4k))] as float2.
    float2* sx = sX[warp];
    {
        const float4* xg = reinterpret_cast<const float4*>(x + (size_t)b * (NS * 2));
        #pragma unroll
        for (int it = 0; it < 4; it++) {
            int fl = it * 32 + lane;             // local float4 index (0..127)
            float4 v = xg[half * 128 + fl];
            int n0 = fl * 2;                     // local sites n0, n0+1
            int l0 = n0 >> 3;
            int k0 = n0 & 7;                     // even, so k0+1 <= 7
            sx[k0 * 32 + (l0 ^ (k0 << 2))] = make_float2(v.x, v.y);
            sx[(k0 + 1) * 32 + (l0 ^ ((k0 + 1) << 2))] = make_float2(v.z, v.w);
        }
        __syncwarp();
    }

    // ---- Pass A: build M per site + lane chunk aggregate (8-deep chain).
    float M00[CHUNK], M01[CHUNK], M11[CHUNK];
    float ca = 1.f, cb = 0.f, cd = 1.f;
    #pragma unroll
    for (int k = 0; k < CHUNK; k++) {
        float2 xv = sx[k * 32 + (lane ^ (k << 2))];
        float rnx = rsqrtf(fmaf(xv.x, xv.x, xv.y * xv.y));
        float u0 = xv.x * rnx, u1 = xv.y * rnx;
        float p = u0 * u0, q = u0 * u1, r = u1 * u1;
        const int ai = half * 256 + k * 32 + lane;
        float4 a4 = sA4a[ai];
        float4 b4 = sA4b[ai];
        float  s1 = sA1[ai];
        float m00 = fmaf(p, a4.x, fmaf(q, a4.y, r * a4.z));
        float m01 = fmaf(p, a4.w, fmaf(q, b4.x, r * b4.y));
        float m11 = fmaf(p, b4.z, fmaf(q, b4.w, r * s1));
        M00[k] = m00; M01[k] = m01; M11[k] = m11;
        float na = ca * m00;
        float nb = fmaf(ca, m01, cb * m11);
        cd = cd * m11;
        ca = na; cb = nb;
    }

    // ---- Interleaved warp Kogge-Stone scans (inclusive prefix + suffix).
    float pa = ca, pb = cb, pd = cd;      // prefix
    float sa = ca, sb = cb, sd = cd;      // suffix
    #pragma unroll
    for (int off = 1; off < 32; off <<= 1) {
        float upa = __shfl_up_sync(0xffffffffu, pa, off);
        float upb = __shfl_up_sync(0xffffffffu, pb, off);
        float upd = __shfl_up_sync(0xffffffffu, pd, off);
        float dna = __shfl_down_sync(0xffffffffu, sa, off);
        float dnb = __shfl_down_sync(0xffffffffu, sb, off);
        float dnd = __shfl_down_sync(0xffffffffu, sd, off);
        if (lane >= off) {
            float ta = upa * pa;
            float tb = fmaf(upa, pb, upb * pd);
            float td = upd * pd;
            pa = ta; pb = tb; pd = td;
        }
        if (lane + off < 32) {
            float ta = sa * dna;
            float tb = fmaf(sa, dnb, sb * dnd);
            float td = sd * dnd;
            sa = ta; sb = tb; sd = td;
        }
    }
    // Exclusive triples (identity at the boundary lanes).
    float ea = __shfl_up_sync(0xffffffffu, pa, 1);
    float eb = __shfl_up_sync(0xffffffffu, pb, 1);
    float ed = __shfl_up_sync(0xffffffffu, pd, 1);
    if (lane == 0) { ea = 1.f; eb = 0.f; ed = 1.f; }
    float ta = __shfl_down_sync(0xffffffffu, sa, 1);
    float tb = __shfl_down_sync(0xffffffffu, sb, 1);
    float td = __shfl_down_sync(0xffffffffu, sd, 1);
    if (lane == 31) { ta = 1.f; tb = 0.f; td = 1.f; }

    // ---- Publish warp totals (inclusive prefix at lane 31) and sync.
    if (lane == 31) {
        sT[warp][0] = pa; sT[warp][1] = pb; sT[warp][2] = pd;
    }
    __syncthreads();

    // C0 = first-half total, C1 = second-half total (for this batch pair).
    float C0a = sT[pair * 2][0],     C0b = sT[pair * 2][1],     C0d = sT[pair * 2][2];
    float C1a = sT[pair * 2 + 1][0], C1b = sT[pair * 2 + 1][1], C1d = sT[pair * 2 + 1][2];
    float T01 = fmaf(C0a, C1b, C0b * C1d);   // full-chain (0,1) entry

    // ---- Global seeds.
    // Prefix row0: half 0 -> local exclusive; half 1 -> C0 ∘ E_loc row0.
    float La, Lb;
    if (half == 0) { La = ea; Lb = eb; }
    else           { La = C0a * ea; Lb = fmaf(C0a, eb, C0b * ed); }
    // Suffix col1: half 1 -> local exclusive tail; half 0 -> E_tail ∘ C1 col1.
    float Sb, Sd;
    if (half == 1) { Sb = tb; Sd = td; }
    else           { Sb = fmaf(ta, C1b, tb * C1d); Sd = td * C1d; }

    // ---- Backward walk: rn = ||S[n+1] col1|| + eps (exact 1 at n = NS-1).
    float rn[CHUNK];
    #pragma unroll
    for (int k = CHUNK - 1; k >= 0; k--) {
        bool last = (half == 1) && (lane == 31) && (k == CHUNK - 1);
        rn[k] = last ? 1.0f : (safe_norm(Sb, Sd) + 1e-6f);
        float nb = fmaf(M00[k], Sb, M01[k] * Sd);
        Sd = M11[k] * Sd;
        Sb = nb;
    }

    // ---- Forward walk: pn = ||P[n-1] row0|| + eps (exact 1 at n = 0);
    //      w = 1/(pn*rn); y[n] = T01*w.
    float sumw = 0.f;
    {
        float ra = La, rb = Lb;
        #pragma unroll
        for (int k = 0; k < CHUNK; k++) {
            bool first = (half == 0) && (lane == 0) && (k == 0);
            float pn = first ? 1.0f : (safe_norm(ra, rb) + 1e-6f);
            float w = __fdividef(1.0f, pn * rn[k]);
            rn[k] = w;
            sumw += w;
            float na = ra * M00[k];
            rb = fmaf(ra, M01[k], rb * M11[k]);
            ra = na;
        }
    }

    // ---- Reduce sum(w) across the warp, then across the warp pair.
    #pragma unroll
    for (int off = 16; off; off >>= 1)
        sumw += __shfl_xor_sync(0xffffffffu, sumw, off);
    if (lane == 0) sWp[warp] = sumw;
    __syncthreads();
    float sumB = sWp[pair * 2] + sWp[pair * 2 + 1];

    // relu + L1 normalization folded into one factor (w > 0, uniform sign).
    float c = scale * T01;
    float f = (c > 0.f) ? __fdividef(c, fmaf(c, sumB, 1e-6f)) : 0.f;

    // ---- Stores: warp covers a contiguous 1KB span.
    float* ob = out + (size_t)b * NS + half * 256 + lane * CHUNK;
    #pragma unroll
    for (int k = 0; k < CHUNK; k += 4) {
        float4 v;
        v.x = rn[k + 0] * f;
        v.y = rn[k + 1] * f;
        v.z = rn[k + 2] * f;
        v.w = rn[k + 3] * f;
        *reinterpret_cast<float4*>(ob + k) = v;
    }
}

extern "C" void kernel_launch(void* const* d_in, const int* in_sizes, int n_in,
                              void* d_out, int out_size) {
    const float* x     = (const float*)d_in[0]; // (B, N, 2)
    const float* mpo   = (const float*)d_in[1]; // (N, 2, 2, 2, 2)
    const float* scale = (const float*)d_in[2]; // scalar
    float* out = (float*)d_out;                 // (B, N)

    int B = in_sizes[0] / (NS * 2);

    prep_A_kernel<<<(NS + 255) / 256, 256>>>(mpo);
    int batches_per_block = WARPS / 2;
    int blocks = (B + batches_per_block - 1) / batches_per_block;
    tdvp_kernel<<<blocks, THREADS>>>(x, scale, out, B);
}

// round 9
// speedup vs baseline: 1.1412x; 1.0598x over previous
#include <cuda_runtime.h>
#include <cstdint>

#define NS 512          // number of sites
#define CHUNK 8         // sites per lane (2 warps x 32 lanes x 8 = 512)
#define WARPS 4         // warps per block = 2 batch slots
#define THREADS 128
#define GRID_BLOCKS 444 // 148 SMs x 3 blocks

// A coefficients, plane-major: g_Ap[j][idx], j = pair*3 + {xx, xy+yx, yy},
// pair 0->(0,0), 1->(0,1), 2->(1,1). Site n = h*256 + l*8 + k lives at
// idx = h*256 + k*32 + l (h = owning-warp half, l = lane, k = local site).
__device__ float g_Ap[9][NS];

__global__ void prep_A_kernel(const float* __restrict__ mpo) {
    int t = blockIdx.x * blockDim.x + threadIdx.x;
    if (t >= NS * 3) return;
    int p = t >> 9, n = t & (NS - 1);
    const float inv = 1.0f / (1.5707963267948966f + 1e-5f); // 1/PI_HALF
    int li = (p == 2) ? 1 : 0;
    int ri = (p == 0) ? 0 : 1;
    const float* m = mpo + n * 16 + li * 8 + ri * 4;        // mpo[n,li,ri,:,:]
    float c0 = atanf(m[0]) * inv;
    float c1 = (atanf(m[1]) + atanf(m[2])) * inv;
    float c2 = atanf(m[3]) * inv;
    int h = n >> 8, l = (n >> 3) & 31, k = n & 7;
    int idx = h * 256 + k * 32 + l;
    g_Ap[3 * p + 0][idx] = c0;
    g_Ap[3 * p + 1][idx] = c1;
    g_Ap[3 * p + 2][idx] = c2;
}

// ||(a,b)|| via rsqrt, safe when a*a+b*b flushes to 0.
__device__ __forceinline__ float safe_norm(float a, float b) {
    float r2 = fmaf(a, a, b * b);
    float nm = r2 * rsqrtf(r2);
    return (r2 > 0.f) ? nm : 0.f;
}

__global__ void __launch_bounds__(THREADS, 3)
tdvp_kernel(const float* __restrict__ x,
            const float* __restrict__ scale_p,
            float* __restrict__ out,
            int B)
{
    __shared__ float2 sX[WARPS][256];     // 8192 B: per-warp x staging
    __shared__ float  sT[WARPS][4];       // warp-chunk totals (a,b,d)
    __shared__ float  sWp[WARPS];         // per-warp partial sums

    const int tid  = threadIdx.x;
    const int lane = tid & 31;
    const int warp = tid >> 5;
    const int half = warp & 1;            // which 256-site half of the batch
    const int pair = warp >> 1;

    const float scale = __ldg(scale_p);

    // ---- Load this lane's A coefficients ONCE (72 registers), coalesced.
    float Ar[CHUNK][9];
    #pragma unroll
    for (int k = 0; k < CHUNK; k++) {
        const int idx = half * 256 + k * 32 + lane;
        #pragma unroll
        for (int j = 0; j < 9; j++) Ar[k][j] = g_Ap[j][idx];
    }

    const int stride = gridDim.x * 2;
    int b = blockIdx.x * 2 + pair;
    // Uniform iteration count across the whole block (max over both pairs).
    const int niter = (B - 1 - blockIdx.x * 2) / stride + 1;

    float2* sx = sX[warp];

    for (int it = 0; it < niter; it++, b += stride) {
        const bool valid = (b < B);

        // ---- Stage x: coalesced float4 loads -> swizzled smem.
        // Local site nl = l*8 + k at sx[k*32 + (l ^ (4k))] as float2.
        __syncwarp();
        if (valid) {
            const float4* xg = reinterpret_cast<const float4*>(x + (size_t)b * (NS * 2));
            #pragma unroll
            for (int t4 = 0; t4 < 4; t4++) {
                int fl = t4 * 32 + lane;             // local float4 index
                float4 v = xg[half * 128 + fl];
                int n0 = fl * 2;
                int l0 = n0 >> 3;
                int k0 = n0 & 7;                     // even => k0+1 <= 7
                sx[k0 * 32 + (l0 ^ (k0 << 2))] = make_float2(v.x, v.y);
                sx[(k0 + 1) * 32 + (l0 ^ ((k0 + 1) << 2))] = make_float2(v.z, v.w);
            }
        }
        __syncwarp();

        // ---- Pass A: build M per site + lane chunk aggregate (8-deep).
        float M00[CHUNK], M01[CHUNK], M11[CHUNK];
        float ca = 1.f, cb = 0.f, cd = 1.f;
        #pragma unroll
        for (int k = 0; k < CHUNK; k++) {
            float2 xv = sx[k * 32 + (lane ^ (k << 2))];
            float rnx = rsqrtf(fmaf(xv.x, xv.x, xv.y * xv.y));
            float u0 = xv.x * rnx, u1 = xv.y * rnx;
            float p = u0 * u0, q = u0 * u1, r = u1 * u1;
            float m00 = fmaf(p, Ar[k][0], fmaf(q, Ar[k][1], r * Ar[k][2]));
            float m01 = fmaf(p, Ar[k][3], fmaf(q, Ar[k][4], r * Ar[k][5]));
            float m11 = fmaf(p, Ar[k][6], fmaf(q, Ar[k][7], r * Ar[k][8]));
            M00[k] = m00; M01[k] = m01; M11[k] = m11;
            float na = ca * m00;
            float nb = fmaf(ca, m01, cb * m11);
            cd = cd * m11;
            ca = na; cb = nb;
        }

        // ---- Interleaved warp Kogge-Stone scans (inclusive prefix+suffix).
        float pa = ca, pb = cb, pd = cd;
        float sa = ca, sb = cb, sd = cd;
        #pragma unroll
        for (int off = 1; off < 32; off <<= 1) {
            float upa = __shfl_up_sync(0xffffffffu, pa, off);
            float upb = __shfl_up_sync(0xffffffffu, pb, off);
            float upd = __shfl_up_sync(0xffffffffu, pd, off);
            float dna = __shfl_down_sync(0xffffffffu, sa, off);
            float dnb = __shfl_down_sync(0xffffffffu, sb, off);
            float dnd = __shfl_down_sync(0xffffffffu, sd, off);
            if (lane >= off) {
                float ta = upa * pa;
                float tb = fmaf(upa, pb, upb * pd);
                float td = upd * pd;
                pa = ta; pb = tb; pd = td;
            }
            if (lane + off < 32) {
                float ta = sa * dna;
                float tb = fmaf(sa, dnb, sb * dnd);
                float td = sd * dnd;
                sa = ta; sb = tb; sd = td;
            }
        }
        // Exclusive triples (identity at boundary lanes).
        float ea = __shfl_up_sync(0xffffffffu, pa, 1);
        float eb = __shfl_up_sync(0xffffffffu, pb, 1);
        float ed = __shfl_up_sync(0xffffffffu, pd, 1);
        if (lane == 0) { ea = 1.f; eb = 0.f; ed = 1.f; }
        float ta2 = __shfl_down_sync(0xffffffffu, sa, 1);
        float tb2 = __shfl_down_sync(0xffffffffu, sb, 1);
        float td2 = __shfl_down_sync(0xffffffffu, sd, 1);
        if (lane == 31) { ta2 = 1.f; tb2 = 0.f; td2 = 1.f; }

        // ---- Publish warp totals (lane 31 inclusive prefix) and sync.
        if (lane == 31) {
            sT[warp][0] = pa; sT[warp][1] = pb; sT[warp][2] = pd;
        }
        __syncthreads();

        float C0a = sT[pair * 2][0],     C0b = sT[pair * 2][1],     C0d = sT[pair * 2][2];
        float C1a = sT[pair * 2 + 1][0], C1b = sT[pair * 2 + 1][1], C1d = sT[pair * 2 + 1][2];
        float T01 = fmaf(C0a, C1b, C0b * C1d);   // full-chain (0,1) entry
        (void)C0d; (void)C1a;

        // ---- Global seeds.
        float La, Lb;
        if (half == 0) { La = ea; Lb = eb; }
        else           { La = C0a * ea; Lb = fmaf(C0a, eb, C0b * ed); }
        float Sb, Sd;
        if (half == 1) { Sb = tb2; Sd = td2; }
        else           { Sb = fmaf(ta2, C1b, tb2 * C1d); Sd = td2 * C1d; }

        // ---- Backward walk: rn = ||S[n+1] col1|| + eps (exact 1 at n=NS-1).
        float rn[CHUNK];
        #pragma unroll
        for (int k = CHUNK - 1; k >= 0; k--) {
            bool lastS = (half == 1) && (lane == 31) && (k == CHUNK - 1);
            rn[k] = lastS ? 1.0f : (safe_norm(Sb, Sd) + 1e-6f);
            float nb = fmaf(M00[k], Sb, M01[k] * Sd);
            Sd = M11[k] * Sd;
            Sb = nb;
        }

        // ---- Forward walk: pn = ||P[n-1] row0|| + eps (exact 1 at n=0);
        //      w = 1/(pn*rn); y[n] = T01*w.
        float sumw = 0.f;
        {
            float ra = La, rb = Lb;
            #pragma unroll
            for (int k = 0; k < CHUNK; k++) {
                bool firstS = (half == 0) && (lane == 0) && (k == 0);
                float pn = firstS ? 1.0f : (safe_norm(ra, rb) + 1e-6f);
                float w = __fdividef(1.0f, pn * rn[k]);
                rn[k] = w;
                sumw += w;
                float na = ra * M00[k];
                rb = fmaf(ra, M01[k], rb * M11[k]);
                ra = na;
            }
        }

        // ---- Reduce sum(w): warp, then warp pair via smem.
        #pragma unroll
        for (int off = 16; off; off >>= 1)
            sumw += __shfl_xor_sync(0xffffffffu, sumw, off);
        if (lane == 0) sWp[warp] = sumw;
        __syncthreads();
        float sumB = sWp[pair * 2] + sWp[pair * 2 + 1];

        // relu + L1 normalization folded into one factor (w > 0).
        float c = scale * T01;
        float f = (c > 0.f) ? __fdividef(c, fmaf(c, sumB, 1e-6f)) : 0.f;

        // ---- Stores: warp covers a contiguous 1KB span.
        if (valid) {
            float* ob = out + (size_t)b * NS + half * 256 + lane * CHUNK;
            #pragma unroll
            for (int k = 0; k < CHUNK; k += 4) {
                float4 v;
                v.x = rn[k + 0] * f;
                v.y = rn[k + 1] * f;
                v.z = rn[k + 2] * f;
                v.w = rn[k + 3] * f;
                *reinterpret_cast<float4*>(ob + k) = v;
            }
        }
    }
}

extern "C" void kernel_launch(void* const* d_in, const int* in_sizes, int n_in,
                              void* d_out, int out_size) {
    const float* x     = (const float*)d_in[0]; // (B, N, 2)
    const float* mpo   = (const float*)d_in[1]; // (N, 2, 2, 2, 2)
    const float* scale = (const float*)d_in[2]; // scalar
    float* out = (float*)d_out;                 // (B, N)

    int B = in_sizes[0] / (NS * 2);

    prep_A_kernel<<<(NS * 3 + 255) / 256, 256>>>(mpo);
    int blocks = GRID_BLOCKS;
    int max_blocks = (B + 1) / 2;       // at least one batch per block
    if (blocks > max_blocks) blocks = max_blocks;
    tdvp_kernel<<<blocks, THREADS>>>(x, scale, out, B);
}

// round 11
// speedup vs baseline: 1.2355x; 1.0826x over previous
#include <cuda_runtime.h>
#include <cstdint>

#define NS 512          // number of sites
#define CHUNK 8         // sites per lane (2 warps x 32 lanes x 8 = 512)
#define WARPS 4         // warps per block = 2 batch slots
#define THREADS 128
#define GRID_BLOCKS 444 // 148 SMs x 3 blocks

// A coefficients, plane-major: g_Ap[j][idx], j = pair*3 + {xx, xy+yx, yy},
// pair 0->(0,0), 1->(0,1), 2->(1,1). Site n = h*256 + l*8 + k lives at
// idx = h*256 + k*32 + l (h = owning-warp half, l = lane, k = local site).
__device__ float g_Ap[9][NS];

__global__ void prep_A_kernel(const float* __restrict__ mpo) {
    int t = blockIdx.x * blockDim.x + threadIdx.x;
    if (t >= NS * 3) return;
    int p = t >> 9, n = t & (NS - 1);
    const float inv = 1.0f / (1.5707963267948966f + 1e-5f); // 1/PI_HALF
    int li = (p == 2) ? 1 : 0;
    int ri = (p == 0) ? 0 : 1;
    const float* m = mpo + n * 16 + li * 8 + ri * 4;        // mpo[n,li,ri,:,:]
    float c0 = atanf(m[0]) * inv;
    float c1 = (atanf(m[1]) + atanf(m[2])) * inv;
    float c2 = atanf(m[3]) * inv;
    int h = n >> 8, l = (n >> 3) & 31, k = n & 7;
    int idx = h * 256 + k * 32 + l;
    g_Ap[3 * p + 0][idx] = c0;
    g_Ap[3 * p + 1][idx] = c1;
    g_Ap[3 * p + 2][idx] = c2;
}

// ||(a,b)|| via rsqrt, safe when a*a+b*b flushes to 0.
__device__ __forceinline__ float safe_norm(float a, float b) {
    float r2 = fmaf(a, a, b * b);
    float nm = r2 * rsqrtf(r2);
    return (r2 > 0.f) ? nm : 0.f;
}

__global__ void __launch_bounds__(THREADS, 3)
tdvp_kernel(const float* __restrict__ x,
            const float* __restrict__ scale_p,
            float* __restrict__ out,
            int B)
{
    __shared__ float2 sX[WARPS][256];     // 8192 B: per-warp x staging
    __shared__ float  sT[WARPS][4];       // warp-chunk totals (a,b,d)
    __shared__ float  sWp[WARPS];         // per-warp partial sums

    const int tid  = threadIdx.x;
    const int lane = tid & 31;
    const int warp = tid >> 5;
    const int half = warp & 1;            // which 256-site half of the batch
    const int pair = warp >> 1;

    const float scale = __ldg(scale_p);

    // ---- Load this lane's A coefficients ONCE (72 registers), coalesced.
    float Ar[CHUNK][9];
    #pragma unroll
    for (int k = 0; k < CHUNK; k++) {
        const int idx = half * 256 + k * 32 + lane;
        #pragma unroll
        for (int j = 0; j < 9; j++) Ar[k][j] = g_Ap[j][idx];
    }

    const int stride = gridDim.x * 2;
    int b = blockIdx.x * 2 + pair;
    // Uniform iteration count across the whole block (max over both pairs).
    const int niter = (B - 1 - blockIdx.x * 2) / stride + 1;

    float2* sx = sX[warp];

    // ---- Prologue prefetch: this warp's 4 float4 of x for the first batch.
    float4 vp[4];
    if (b < B) {
        const float4* xg = reinterpret_cast<const float4*>(x + (size_t)b * (NS * 2));
        #pragma unroll
        for (int t4 = 0; t4 < 4; t4++)
            vp[t4] = xg[half * 128 + t4 * 32 + lane];
    }

    for (int it = 0; it < niter; it++, b += stride) {
        const bool valid = (b < B);

        // ---- Commit prefetched x -> swizzled smem.
        // Local site nl = l*8 + k at sx[k*32 + (l ^ (4k))] as float2.
        __syncwarp();    // prior iteration's sx reads complete
        #pragma unroll
        for (int t4 = 0; t4 < 4; t4++) {
            int fl = t4 * 32 + lane;             // local float4 index
            int n0 = fl * 2;
            int l0 = n0 >> 3;
            int k0 = n0 & 7;                     // even => k0+1 <= 7
            sx[k0 * 32 + (l0 ^ (k0 << 2))] = make_float2(vp[t4].x, vp[t4].y);
            sx[(k0 + 1) * 32 + (l0 ^ ((k0 + 1) << 2))] = make_float2(vp[t4].z, vp[t4].w);
        }
        __syncwarp();

        // ---- Issue next iteration's prefetch (overlaps with compute below).
        {
            int bn = b + stride;
            if (bn < B) {
                const float4* xgn = reinterpret_cast<const float4*>(x + (size_t)bn * (NS * 2));
                #pragma unroll
                for (int t4 = 0; t4 < 4; t4++)
                    vp[t4] = xgn[half * 128 + t4 * 32 + lane];
            }
        }

        // ---- Pass A: build M per site + lane chunk aggregate (8-deep).
        float M00[CHUNK], M01[CHUNK], M11[CHUNK];
        float ca = 1.f, cb = 0.f, cd = 1.f;
        #pragma unroll
        for (int k = 0; k < CHUNK; k++) {
            float2 xv = sx[k * 32 + (lane ^ (k << 2))];
            float rnx = rsqrtf(fmaf(xv.x, xv.x, xv.y * xv.y));
            float u0 = xv.x * rnx, u1 = xv.y * rnx;
            float p = u0 * u0, q = u0 * u1, r = u1 * u1;
            float m00 = fmaf(p, Ar[k][0], fmaf(q, Ar[k][1], r * Ar[k][2]));
            float m01 = fmaf(p, Ar[k][3], fmaf(q, Ar[k][4], r * Ar[k][5]));
            float m11 = fmaf(p, Ar[k][6], fmaf(q, Ar[k][7], r * Ar[k][8]));
            M00[k] = m00; M01[k] = m01; M11[k] = m11;
            float na = ca * m00;
            float nb = fmaf(ca, m01, cb * m11);
            cd = cd * m11;
            ca = na; cb = nb;
        }

        // ---- Interleaved warp Kogge-Stone scans (inclusive prefix+suffix).
        float pa = ca, pb = cb, pd = cd;
        float sa = ca, sb = cb, sd = cd;
        #pragma unroll
        for (int off = 1; off < 32; off <<= 1) {
            float upa = __shfl_up_sync(0xffffffffu, pa, off);
            float upb = __shfl_up_sync(0xffffffffu, pb, off);
            float upd = __shfl_up_sync(0xffffffffu, pd, off);
            float dna = __shfl_down_sync(0xffffffffu, sa, off);
            float dnb = __shfl_down_sync(0xffffffffu, sb, off);
            float dnd = __shfl_down_sync(0xffffffffu, sd, off);
            if (lane >= off) {
                float ta = upa * pa;
                float tb = fmaf(upa, pb, upb * pd);
                float td = upd * pd;
                pa = ta; pb = tb; pd = td;
            }
            if (lane + off < 32) {
                float ta = sa * dna;
                float tb = fmaf(sa, dnb, sb * dnd);
                float td = sd * dnd;
                sa = ta; sb = tb; sd = td;
            }
        }
        // Exclusive triples (identity at boundary lanes).
        float ea = __shfl_up_sync(0xffffffffu, pa, 1);
        float eb = __shfl_up_sync(0xffffffffu, pb, 1);
        float ed = __shfl_up_sync(0xffffffffu, pd, 1);
        if (lane == 0) { ea = 1.f; eb = 0.f; ed = 1.f; }
        float ta2 = __shfl_down_sync(0xffffffffu, sa, 1);
        float tb2 = __shfl_down_sync(0xffffffffu, sb, 1);
        float td2 = __shfl_down_sync(0xffffffffu, sd, 1);
        if (lane == 31) { ta2 = 1.f; tb2 = 0.f; td2 = 1.f; }

        // ---- Publish warp totals (lane 31 inclusive prefix) and sync.
        if (lane == 31) {
            sT[warp][0] = pa; sT[warp][1] = pb; sT[warp][2] = pd;
        }
        __syncthreads();

        float C0a = sT[pair * 2][0],     C0b = sT[pair * 2][1];
        float C1b = sT[pair * 2 + 1][1], C1d = sT[pair * 2 + 1][2];
        float T01 = fmaf(C0a, C1b, C0b * C1d);   // full-chain (0,1) entry

        // ---- Global seeds.
        float La, Lb;
        if (half == 0) { La = ea; Lb = eb; }
        else           { La = C0a * ea; Lb = fmaf(C0a, eb, C0b * ed); }
        float Sb, Sd;
        if (half == 1) { Sb = tb2; Sd = td2; }
        else           { Sb = fmaf(ta2, C1b, tb2 * C1d); Sd = td2 * C1d; }

        // ---- Backward walk: rn = ||S[n+1] col1|| + eps (exact 1 at n=NS-1).
        float rn[CHUNK];
        #pragma unroll
        for (int k = CHUNK - 1; k >= 0; k--) {
            bool lastS = (half == 1) && (lane == 31) && (k == CHUNK - 1);
            rn[k] = lastS ? 1.0f : (safe_norm(Sb, Sd) + 1e-6f);
            float nb = fmaf(M00[k], Sb, M01[k] * Sd);
            Sd = M11[k] * Sd;
            Sb = nb;
        }

        // ---- Forward walk: pn = ||P[n-1] row0|| + eps (exact 1 at n=0);
        //      w = 1/(pn*rn); y[n] = T01*w.
        float sumw = 0.f;
        {
            float ra = La, rb = Lb;
            #pragma unroll
            for (int k = 0; k < CHUNK; k++) {
                bool firstS = (half == 0) && (lane == 0) && (k == 0);
                float pn = firstS ? 1.0f : (safe_norm(ra, rb) + 1e-6f);
                float w = __fdividef(1.0f, pn * rn[k]);
                rn[k] = w;
                sumw += w;
                float na = ra * M00[k];
                rb = fmaf(ra, M01[k], rb * M11[k]);
                ra = na;
            }
        }

        // ---- Reduce sum(w): warp, then warp pair via smem.
        #pragma unroll
        for (int off = 16; off; off >>= 1)
            sumw += __shfl_xor_sync(0xffffffffu, sumw, off);
        if (lane == 0) sWp[warp] = sumw;
        __syncthreads();
        float sumB = sWp[pair * 2] + sWp[pair * 2 + 1];

        // relu + L1 normalization folded into one factor (w > 0).
        float c = scale * T01;
        float f = (c > 0.f) ? __fdividef(c, fmaf(c, sumB, 1e-6f)) : 0.f;

        // ---- Stores: warp covers a contiguous 1KB span.
        if (valid) {
            float* ob = out + (size_t)b * NS + half * 256 + lane * CHUNK;
            #pragma unroll
            for (int k = 0; k < CHUNK; k += 4) {
                float4 v;
                v.x = rn[k + 0] * f;
                v.y = rn[k + 1] * f;
                v.z = rn[k + 2] * f;
                v.w = rn[k + 3] * f;
                *reinterpret_cast<float4*>(ob + k) = v;
            }
        }
    }
}

extern "C" void kernel_launch(void* const* d_in, const int* in_sizes, int n_in,
                              void* d_out, int out_size) {
    const float* x     = (const float*)d_in[0]; // (B, N, 2)
    const float* mpo   = (const float*)d_in[1]; // (N, 2, 2, 2, 2)
    const float* scale = (const float*)d_in[2]; // scalar
    float* out = (float*)d_out;                 // (B, N)

    int B = in_sizes[0] / (NS * 2);

    prep_A_kernel<<<(NS * 3 + 255) / 256, 256>>>(mpo);
    int blocks = GRID_BLOCKS;
    int max_blocks = (B + 1) / 2;       // at least one batch per block
    if (blocks > max_blocks) blocks = max_blocks;
    tdvp_kernel<<<blocks, THREADS>>>(x, scale, out, B);
}